// round 14
// baseline (speedup 1.0000x reference)
#include <cuda_runtime.h>
#include <cuda_fp16.h>
#include <cstdint>

// Shapes fixed by the reference
#define N_NODES  100000
#define IN_DIM   128
#define KDIM     256          // 2*IN_DIM
#define HID      64
#define WARPS    5            // warps per block (one block per SM)
#define NTHREADS (WARPS*32)
#define CHUNK_E  32           // edges per warp chunk (M=32)
#define LDAS     132          // A slab row stride in words (128 data + 4 pad)
#define LDW      132          // W1t row stride in words (128 data + 4 pad)
#define GRID     152          // 1 block per SM

#define A_SLAB_WORDS (CHUNK_E*LDAS)           // 4224 words = 16.9 KB
#define SMEM_BYTES ((WARPS*2*A_SLAB_WORDS + HID*LDW)*4 + (64+64+1)*4)

// fp16 copy of z, gathered via cp.async (25.6 MB static scratch)
__device__ __half zh_g[N_NODES * IN_DIM];

__global__ void convert_z_kernel(const float* __restrict__ z, int n) {
    const int stride = gridDim.x * blockDim.x;
    const int n4 = n >> 2;
    const float4* z4 = reinterpret_cast<const float4*>(z);
    __half2* o2 = reinterpret_cast<__half2*>(zh_g);
    for (int i = blockIdx.x * blockDim.x + threadIdx.x; i < n4; i += stride) {
        float4 v = z4[i];
        o2[i * 2 + 0] = __floats2half2_rn(v.x, v.y);
        o2[i * 2 + 1] = __floats2half2_rn(v.z, v.w);
    }
}

__device__ __forceinline__ void mma_fp16(float* c, const uint32_t* a,
                                         uint32_t b0, uint32_t b1) {
    asm volatile(
        "mma.sync.aligned.m16n8k16.row.col.f32.f16.f16.f32 "
        "{%0,%1,%2,%3}, {%4,%5,%6,%7}, {%8,%9}, {%0,%1,%2,%3};"
        : "+f"(c[0]), "+f"(c[1]), "+f"(c[2]), "+f"(c[3])
        : "r"(a[0]), "r"(a[1]), "r"(a[2]), "r"(a[3]), "r"(b0), "r"(b1));
}

struct GatherCtx {
    const int* e32;
    const long long* e64;
    bool is64;
    const char* zb;
    int NE, lane, halfSel, sub;
};

// Issue cp.async gather of one 32-edge chunk into the slab at `slab` (no waits).
__device__ __forceinline__ void issue_gather(const GatherCtx& c, int chunk,
                                             uint32_t* slab) {
    const int ge = chunk * CHUNK_E + c.lane;
    long long sIdx = 0, dIdx = 0;
    if (ge < c.NE) {
        if (c.is64) { sIdx = c.e64[ge]; dIdx = c.e64[(long long)c.NE + ge]; }
        else        { sIdx = (long long)c.e32[ge]; dIdx = (long long)c.e32[c.NE + ge]; }
    }
    #pragma unroll 8
    for (int i = 0; i < 32; i++) {
        const long long s = __shfl_sync(0xffffffffu, sIdx, i);
        const long long d = __shfl_sync(0xffffffffu, dIdx, i);
        const long long row = c.halfSel ? d : s;
        const char* src = c.zb + (row << 8) + c.sub * 16;
        char* dstp = reinterpret_cast<char*>(slab)
                   + i * (LDAS * 4) + c.halfSel * 256 + c.sub * 16;
        const uint32_t daddr = (uint32_t)__cvta_generic_to_shared(dstp);
        asm volatile("cp.async.cg.shared.global [%0], [%1], 16;\n"
                     :: "r"(daddr), "l"(src));
    }
    asm volatile("cp.async.commit_group;\n");
}

__global__ __launch_bounds__(NTHREADS, 1)
void mask_predictor_kernel(const void* __restrict__ eidx_raw,
                           const float* __restrict__ W1,
                           const float* __restrict__ b1,
                           const float* __restrict__ W2,
                           const float* __restrict__ b2,
                           float* __restrict__ out,
                           int NE) {
    extern __shared__ unsigned char smem_raw[];
    uint32_t* As32  = reinterpret_cast<uint32_t*>(smem_raw);     // [WARPS*2 slabs]
    uint32_t* W1t32 = As32 + WARPS * 2 * A_SLAB_WORDS;           // [64][132] words
    float*    b1s   = reinterpret_cast<float*>(W1t32 + HID * LDW);
    float*    w2s   = b1s + 64;
    float*    b2s   = w2s + 64;
    __half*   W1th  = reinterpret_cast<__half*>(W1t32);          // halves, stride 264

    const int tid  = threadIdx.x;
    const int warp = tid >> 5;
    const int lane = tid & 31;
    const int g    = lane >> 2;   // groupID (0..7)
    const int m    = lane & 3;    // thread-in-group (0..3)

    // ---- Detect edge_index dtype (int64 vs int32) uniformly ----
    const int*       e32 = reinterpret_cast<const int*>(eidx_raw);
    const long long* e64 = reinterpret_cast<const long long*>(eidx_raw);
    bool is64 = true;
    #pragma unroll
    for (int i = 1; i < 32; i += 2) if (e32[i] != 0) is64 = false;

    // ---- Stage W1^T (fp16), b1, W2, b2 (read-only after this barrier) ----
    for (int i = tid; i < KDIM * HID; i += NTHREADS) {
        const int k = i >> 6, n = i & 63;
        W1th[n * (LDW * 2) + k] = __float2half(W1[i]);
    }
    if (tid < 64) { b1s[tid] = b1[tid]; w2s[tid] = W2[tid]; }
    if (tid == 64) { b2s[0] = b2[0]; }
    __syncthreads();

    uint32_t* slab0 = As32 + (warp * 2 + 0) * A_SLAB_WORDS;
    uint32_t* slab1 = As32 + (warp * 2 + 1) * A_SLAB_WORDS;

    GatherCtx ctx;
    ctx.e32 = e32; ctx.e64 = e64; ctx.is64 = is64;
    ctx.zb = reinterpret_cast<const char*>(zh_g);
    ctx.NE = NE;
    ctx.lane = lane;
    ctx.halfSel = lane >> 4;
    ctx.sub = lane & 15;

    const int nChunks = (NE + CHUNK_E - 1) / CHUNK_E;
    const int wStride = GRID * WARPS;

    // Per-warp double-buffered pipeline: one gather group always in flight.
    // The wait at loop top has had a full chunk's compute time to complete.
    int chunk = blockIdx.x * WARPS + warp;
    int buf = 0;
    if (chunk < nChunks) issue_gather(ctx, chunk, slab0);

    for (; chunk < nChunks; chunk += wStride) {
        const int nxt = chunk + wStride;
        if (nxt < nChunks) {
            issue_gather(ctx, nxt, buf ? slab0 : slab1);
            asm volatile("cp.async.wait_group 1;\n" ::: "memory");
        } else {
            asm volatile("cp.async.wait_group 0;\n" ::: "memory");
        }
        __syncwarp();   // make lane-written rows visible warp-wide

        uint32_t* myAs = buf ? slab1 : slab0;

        // ---- GEMM: 32 edges x 64 cols, fp16 m16n8k16, fp32 acc ----
        float acc[2][8][4];
        #pragma unroll
        for (int mt = 0; mt < 2; mt++)
            #pragma unroll
            for (int nt = 0; nt < 8; nt++)
                #pragma unroll
                for (int r = 0; r < 4; r++) acc[mt][nt][r] = 0.f;

        #pragma unroll 4
        for (int kt = 0; kt < 16; kt++) {
            const int kw = kt * 8 + m;
            uint32_t a[2][4];
            #pragma unroll
            for (int mt = 0; mt < 2; mt++) {
                const int base = (mt * 16 + g) * LDAS;
                a[mt][0] = myAs[base + kw];
                a[mt][1] = myAs[base + 8 * LDAS + kw];
                a[mt][2] = myAs[base + kw + 4];
                a[mt][3] = myAs[base + 8 * LDAS + kw + 4];
            }
            #pragma unroll
            for (int nt = 0; nt < 8; nt++) {
                const uint32_t b0  = W1t32[(nt * 8 + g) * LDW + kw];
                const uint32_t b1v = W1t32[(nt * 8 + g) * LDW + kw + 4];
                mma_fp16(acc[0][nt], a[0], b0, b1v);
                mma_fp16(acc[1][nt], a[1], b0, b1v);
            }
        }

        // ---- Epilogue: bias + ReLU + W2 dot + sigmoid ----
        float p[4] = {0.f, 0.f, 0.f, 0.f};  // rows g, g+8, g+16, g+24
        #pragma unroll
        for (int mt = 0; mt < 2; mt++) {
            #pragma unroll
            for (int nt = 0; nt < 8; nt++) {
                const int c = nt * 8 + 2 * m;
                const float ba = b1s[c], bb = b1s[c + 1];
                const float wa = w2s[c], wb = w2s[c + 1];
                float h;
                h = acc[mt][nt][0] + ba; p[mt * 2 + 0] += fmaxf(h, 0.f) * wa;
                h = acc[mt][nt][1] + bb; p[mt * 2 + 0] += fmaxf(h, 0.f) * wb;
                h = acc[mt][nt][2] + ba; p[mt * 2 + 1] += fmaxf(h, 0.f) * wa;
                h = acc[mt][nt][3] + bb; p[mt * 2 + 1] += fmaxf(h, 0.f) * wb;
            }
        }
        #pragma unroll
        for (int j = 0; j < 4; j++) {
            p[j] += __shfl_xor_sync(0xffffffffu, p[j], 1);
            p[j] += __shfl_xor_sync(0xffffffffu, p[j], 2);
        }
        if (m == 0) {
            const float bias2 = b2s[0];
            const int base = chunk * CHUNK_E;
            #pragma unroll
            for (int j = 0; j < 4; j++) {
                const int e = base + (j >> 1) * 16 + (j & 1) * 8 + g;
                if (e < NE)
                    out[e] = 1.f / (1.f + __expf(-(p[j] + bias2)));
            }
        }
        buf ^= 1;
    }
}

extern "C" void kernel_launch(void* const* d_in, const int* in_sizes, int n_in,
                              void* d_out, int out_size) {
    const float* z    = (const float*)d_in[0];
    const void*  eidx = d_in[1];
    const float* W1   = (const float*)d_in[2];
    const float* b1   = (const float*)d_in[3];
    const float* W2   = (const float*)d_in[4];
    const float* b2   = (const float*)d_in[5];
    float*       out  = (float*)d_out;

    const int NE = in_sizes[1] / 2;  // edge_index is (2, E)
    const int nZ = in_sizes[0];      // N_NODES * IN_DIM

    static bool attr_set = false;
    if (!attr_set) {
        cudaFuncSetAttribute(mask_predictor_kernel,
                             cudaFuncAttributeMaxDynamicSharedMemorySize, SMEM_BYTES);
        attr_set = true;
    }

    convert_z_kernel<<<152, 256>>>(z, nZ);
    mask_predictor_kernel<<<GRID, NTHREADS, SMEM_BYTES>>>(eidx, W1, b1, W2, b2, out, NE);
}

// round 15
// speedup vs baseline: 1.5791x; 1.5791x over previous
#include <cuda_runtime.h>
#include <cuda_fp16.h>
#include <cstdint>

// Shapes fixed by the reference
#define N_NODES  100000
#define IN_DIM   128
#define KDIM     256          // 2*IN_DIM
#define HID      64
#define WARPS    11           // warps per block (one block per SM)
#define NTHREADS (WARPS*32)
#define CHUNK_E  32           // edges per warp chunk (M=32)
#define LDAS     132          // A slab row stride in words (128 data + 4 pad)
#define LDW      132          // W1t row stride in words (128 data + 4 pad)
#define GRID     152          // 1 block per SM

#define A_SLAB_WORDS (CHUNK_E*LDAS)
#define SMEM_BYTES ((WARPS*A_SLAB_WORDS + HID*LDW)*4 + (64+64+1)*4)

// fp16 copy of z, gathered via cp.async (25.6 MB static scratch)
__device__ __half zh_g[N_NODES * IN_DIM];

__global__ void convert_z_kernel(const float* __restrict__ z, int n) {
    const int stride = gridDim.x * blockDim.x;
    const int n4 = n >> 2;
    const float4* z4 = reinterpret_cast<const float4*>(z);
    __half2* o2 = reinterpret_cast<__half2*>(zh_g);
    for (int i = blockIdx.x * blockDim.x + threadIdx.x; i < n4; i += stride) {
        float4 v = z4[i];
        o2[i * 2 + 0] = __floats2half2_rn(v.x, v.y);
        o2[i * 2 + 1] = __floats2half2_rn(v.z, v.w);
    }
}

__device__ __forceinline__ void mma_fp16(float* c, const uint32_t* a,
                                         uint32_t b0, uint32_t b1) {
    asm volatile(
        "mma.sync.aligned.m16n8k16.row.col.f32.f16.f16.f32 "
        "{%0,%1,%2,%3}, {%4,%5,%6,%7}, {%8,%9}, {%0,%1,%2,%3};"
        : "+f"(c[0]), "+f"(c[1]), "+f"(c[2]), "+f"(c[3])
        : "r"(a[0]), "r"(a[1]), "r"(a[2]), "r"(a[3]), "r"(b0), "r"(b1));
}

#define LDSM_X4(r0, r1, r2, r3, addr) \
    asm volatile("ldmatrix.sync.aligned.m8n8.x4.shared.b16 {%0,%1,%2,%3}, [%4];" \
        : "=r"(r0), "=r"(r1), "=r"(r2), "=r"(r3) : "r"(addr))

struct GatherCtx {
    const int* e32;
    const long long* e64;
    bool is64;
    const char* zb;
    uint32_t* As32;           // this warp's 32-row slab
    int NE, lane, halfSel, sub;
};

// Issue cp.async gather of one 32-edge chunk into this warp's slab (no waits).
__device__ __forceinline__ void issue_gather(const GatherCtx& c, int chunk) {
    const int ge = chunk * CHUNK_E + c.lane;
    long long sIdx = 0, dIdx = 0;
    if (ge < c.NE) {
        if (c.is64) { sIdx = c.e64[ge]; dIdx = c.e64[(long long)c.NE + ge]; }
        else        { sIdx = (long long)c.e32[ge]; dIdx = (long long)c.e32[c.NE + ge]; }
    }
    #pragma unroll 8
    for (int i = 0; i < 32; i++) {
        const long long s = __shfl_sync(0xffffffffu, sIdx, i);
        const long long d = __shfl_sync(0xffffffffu, dIdx, i);
        const long long row = c.halfSel ? d : s;
        const char* src = c.zb + (row << 8) + c.sub * 16;
        char* dstp = reinterpret_cast<char*>(c.As32)
                   + i * (LDAS * 4) + c.halfSel * 256 + c.sub * 16;
        const uint32_t daddr = (uint32_t)__cvta_generic_to_shared(dstp);
        asm volatile("cp.async.cg.shared.global [%0], [%1], 16;\n"
                     :: "r"(daddr), "l"(src));
    }
    asm volatile("cp.async.commit_group;\n");
}

__global__ __launch_bounds__(NTHREADS, 1)
void mask_predictor_kernel(const void* __restrict__ eidx_raw,
                           const float* __restrict__ W1,
                           const float* __restrict__ b1,
                           const float* __restrict__ W2,
                           const float* __restrict__ b2,
                           float* __restrict__ out,
                           int NE) {
    extern __shared__ unsigned char smem_raw[];
    uint32_t* As32  = reinterpret_cast<uint32_t*>(smem_raw);     // [352][132] words
    uint32_t* W1t32 = As32 + WARPS * A_SLAB_WORDS;               // [64][132] words
    float*    b1s   = reinterpret_cast<float*>(W1t32 + HID * LDW);
    float*    w2s   = b1s + 64;
    float*    b2s   = w2s + 64;
    __half*   W1th  = reinterpret_cast<__half*>(W1t32);          // halves, stride 264

    const int tid  = threadIdx.x;
    const int warp = tid >> 5;
    const int lane = tid & 31;
    const int g    = lane >> 2;   // groupID (0..7)
    const int m    = lane & 3;    // thread-in-group (0..3)

    // ---- Detect edge_index dtype (int64 vs int32) uniformly ----
    const int*       e32 = reinterpret_cast<const int*>(eidx_raw);
    const long long* e64 = reinterpret_cast<const long long*>(eidx_raw);
    bool is64 = true;
    #pragma unroll
    for (int i = 1; i < 32; i += 2) if (e32[i] != 0) is64 = false;

    // ---- Stage W1^T (fp16), b1, W2, b2 (read-only after this barrier) ----
    for (int i = tid; i < KDIM * HID; i += NTHREADS) {
        const int k = i >> 6, n = i & 63;
        W1th[n * (LDW * 2) + k] = __float2half(W1[i]);
    }
    if (tid < 64) { b1s[tid] = b1[tid]; w2s[tid] = W2[tid]; }
    if (tid == 64) { b2s[0] = b2[0]; }
    __syncthreads();

    uint32_t* myAs = As32 + warp * A_SLAB_WORDS;

    // ---- Per-lane ldmatrix base addresses (byte, shared space) ----
    // A tile mt: M0 rows0-7@k0-7, M1 rows8-15@k0-7, M2 rows0-7@k8-15, M3 rows8-15@k8-15
    //   lane -> row = lane&15, kbyte = (lane>>4)*16
    const uint32_t aRow   = (uint32_t)(lane & 15);
    const uint32_t aKoff  = (uint32_t)((lane >> 4) * 16);
    uint32_t aBase[2];
    #pragma unroll
    for (int mt = 0; mt < 2; mt++) {
        aBase[mt] = (uint32_t)__cvta_generic_to_shared(
            reinterpret_cast<char*>(myAs) + (mt * 16 + aRow) * (LDAS * 4)) + aKoff;
    }
    // B pair p covers nt=2p,2p+1: M0 rows(2p)*8@k0-7, M1 same@k8-15,
    //   M2 rows(2p+1)*8@k0-7, M3 same@k8-15
    //   lane -> q=lane>>3: nrow=(2p + (q>>1))*8 + (lane&7), kbyte=(q&1)*16
    const uint32_t q      = (uint32_t)(lane >> 3);
    const uint32_t bRowIn = ((q >> 1) * 8) + (uint32_t)(lane & 7);
    const uint32_t bKoff  = (q & 1) * 16;
    uint32_t bBase[4];
    #pragma unroll
    for (int p = 0; p < 4; p++) {
        bBase[p] = (uint32_t)__cvta_generic_to_shared(
            reinterpret_cast<char*>(W1t32) + (p * 16 + bRowIn) * (LDW * 4)) + bKoff;
    }

    GatherCtx ctx;
    ctx.e32 = e32; ctx.e64 = e64; ctx.is64 = is64;
    ctx.zb = reinterpret_cast<const char*>(zh_g);
    ctx.As32 = myAs; ctx.NE = NE;
    ctx.lane = lane;
    ctx.halfSel = lane >> 4;
    ctx.sub = lane & 15;

    const int nChunks = (NE + CHUNK_E - 1) / CHUNK_E;
    const int wStride = GRID * WARPS;

    int chunk = blockIdx.x * WARPS + warp;
    if (chunk < nChunks) issue_gather(ctx, chunk);

    for (; chunk < nChunks; chunk += wStride) {
        asm volatile("cp.async.wait_group 0;\n" ::: "memory");
        __syncwarp();   // make lane-written rows visible warp-wide

        // ---- GEMM: 32 edges x 64 cols via ldmatrix + m16n8k16 ----
        float acc[2][8][4];
        #pragma unroll
        for (int mt = 0; mt < 2; mt++)
            #pragma unroll
            for (int nt = 0; nt < 8; nt++)
                #pragma unroll
                for (int r = 0; r < 4; r++) acc[mt][nt][r] = 0.f;

        #pragma unroll 4
        for (int kt = 0; kt < 16; kt++) {
            const uint32_t kOff = (uint32_t)(kt * 32);
            uint32_t a[2][4];
            LDSM_X4(a[0][0], a[0][1], a[0][2], a[0][3], aBase[0] + kOff);
            LDSM_X4(a[1][0], a[1][1], a[1][2], a[1][3], aBase[1] + kOff);
            uint32_t b[4][4];   // [pair]{b0(nt=2p),b1(2p),b0(2p+1),b1(2p+1)}
            LDSM_X4(b[0][0], b[0][1], b[0][2], b[0][3], bBase[0] + kOff);
            LDSM_X4(b[1][0], b[1][1], b[1][2], b[1][3], bBase[1] + kOff);
            LDSM_X4(b[2][0], b[2][1], b[2][2], b[2][3], bBase[2] + kOff);
            LDSM_X4(b[3][0], b[3][1], b[3][2], b[3][3], bBase[3] + kOff);
            #pragma unroll
            for (int p = 0; p < 4; p++) {
                mma_fp16(acc[0][2*p+0], a[0], b[p][0], b[p][1]);
                mma_fp16(acc[1][2*p+0], a[1], b[p][0], b[p][1]);
                mma_fp16(acc[0][2*p+1], a[0], b[p][2], b[p][3]);
                mma_fp16(acc[1][2*p+1], a[1], b[p][2], b[p][3]);
            }
        }

        __syncwarp();   // all lanes done reading As before overwrite

        // ---- Prefetch next chunk's gather; lands during epilogue + peers ----
        const int nxt = chunk + wStride;
        if (nxt < nChunks) issue_gather(ctx, nxt);

        // ---- Epilogue: bias + ReLU + W2 dot + sigmoid ----
        float p4[4] = {0.f, 0.f, 0.f, 0.f};  // rows g, g+8, g+16, g+24
        #pragma unroll
        for (int mt = 0; mt < 2; mt++) {
            #pragma unroll
            for (int nt = 0; nt < 8; nt++) {
                const int c = nt * 8 + 2 * m;
                const float ba = b1s[c], bb = b1s[c + 1];
                const float wa = w2s[c], wb = w2s[c + 1];
                float h;
                h = acc[mt][nt][0] + ba; p4[mt * 2 + 0] += fmaxf(h, 0.f) * wa;
                h = acc[mt][nt][1] + bb; p4[mt * 2 + 0] += fmaxf(h, 0.f) * wb;
                h = acc[mt][nt][2] + ba; p4[mt * 2 + 1] += fmaxf(h, 0.f) * wa;
                h = acc[mt][nt][3] + bb; p4[mt * 2 + 1] += fmaxf(h, 0.f) * wb;
            }
        }
        #pragma unroll
        for (int j = 0; j < 4; j++) {
            p4[j] += __shfl_xor_sync(0xffffffffu, p4[j], 1);
            p4[j] += __shfl_xor_sync(0xffffffffu, p4[j], 2);
        }
        if (m == 0) {
            const float bias2 = b2s[0];
            const int base = chunk * CHUNK_E;
            #pragma unroll
            for (int j = 0; j < 4; j++) {
                const int e = base + (j >> 1) * 16 + (j & 1) * 8 + g;
                if (e < NE)
                    out[e] = 1.f / (1.f + __expf(-(p4[j] + bias2)));
            }
        }
    }
}

extern "C" void kernel_launch(void* const* d_in, const int* in_sizes, int n_in,
                              void* d_out, int out_size) {
    const float* z    = (const float*)d_in[0];
    const void*  eidx = d_in[1];
    const float* W1   = (const float*)d_in[2];
    const float* b1   = (const float*)d_in[3];
    const float* W2   = (const float*)d_in[4];
    const float* b2   = (const float*)d_in[5];
    float*       out  = (float*)d_out;

    const int NE = in_sizes[1] / 2;  // edge_index is (2, E)
    const int nZ = in_sizes[0];      // N_NODES * IN_DIM

    static bool attr_set = false;
    if (!attr_set) {
        cudaFuncSetAttribute(mask_predictor_kernel,
                             cudaFuncAttributeMaxDynamicSharedMemorySize, SMEM_BYTES);
        attr_set = true;
    }

    convert_z_kernel<<<152, 256>>>(z, nZ);
    mask_predictor_kernel<<<GRID, NTHREADS, SMEM_BYTES>>>(eidx, W1, b1, W2, b2, out, NE);
}